// round 1
// baseline (speedup 1.0000x reference)
#include <cuda_runtime.h>
#include <math.h>

#define NIN  4096
#define MOUT 16384
#define NB   4
#define CIN  256
#define CO   128

// ---------------- device scratch (no allocations allowed) ----------------
__device__ __align__(16) float g_Wf1[CO * CIN];
__device__ __align__(16) float g_Wf2[CO * CO];
__device__ __align__(16) float g_Wf3[CO * CO];
__device__ __align__(16) float g_bf[3][CO];
__device__ __align__(16) float g_feat1[NB * CO * NIN];
__device__ __align__(16) float g_feat2[NB * CO * NIN];
__device__ __align__(16) float g_featT[NB * NIN * CO];   // (B, NIN, CO) for gather
__device__ float4 g_pts[NB * NIN];                        // (-2x,-2y,-2z, |p|^2)

// ---------------- fold BN into weights/bias ----------------
__global__ void fold_kernel(
    const float* __restrict__ w1, const float* __restrict__ b1, const float* __restrict__ gg1,
    const float* __restrict__ be1, const float* __restrict__ rm1, const float* __restrict__ rv1,
    const float* __restrict__ w2, const float* __restrict__ b2, const float* __restrict__ gg2,
    const float* __restrict__ be2, const float* __restrict__ rm2, const float* __restrict__ rv2,
    const float* __restrict__ w3, const float* __restrict__ b3, const float* __restrict__ gg3,
    const float* __restrict__ be3, const float* __restrict__ rm3, const float* __restrict__ rv3)
{
    const float eps = 1e-5f;
    int idx = blockIdx.x * blockDim.x + threadIdx.x;
    if (idx < CO * CIN) {
        int o = idx / CIN;
        g_Wf1[idx] = gg1[o] / sqrtf(rv1[o] + eps) * w1[idx];
    } else if (idx < CO * CIN + CO * CO) {
        int i = idx - CO * CIN; int o = i / CO;
        g_Wf2[i] = gg2[o] / sqrtf(rv2[o] + eps) * w2[i];
    } else if (idx < CO * CIN + 2 * CO * CO) {
        int i = idx - CO * CIN - CO * CO; int o = i / CO;
        g_Wf3[i] = gg3[o] / sqrtf(rv3[o] + eps) * w3[i];
    }
    if (idx < CO) {
        float s1 = gg1[idx] / sqrtf(rv1[idx] + eps);
        g_bf[0][idx] = s1 * (b1[idx] - rm1[idx]) + be1[idx];
        float s2 = gg2[idx] / sqrtf(rv2[idx] + eps);
        g_bf[1][idx] = s2 * (b2[idx] - rm2[idx]) + be2[idx];
        float s3 = gg3[idx] / sqrtf(rv3[idx] + eps);
        g_bf[2][idx] = s3 * (b3[idx] - rm3[idx]) + be3[idx];
    }
}

// ---------------- transform input points for the distance trick ----------------
__global__ void pts_kernel(const float* __restrict__ xyzin)
{
    int idx = blockIdx.x * blockDim.x + threadIdx.x;
    if (idx < NB * NIN) {
        const float* p = xyzin + (size_t)idx * 3;
        float x = p[0], y = p[1], z = p[2];
        g_pts[idx] = make_float4(-2.f * x, -2.f * y, -2.f * z, x * x + y * y + z * z);
    }
}

// ---------------- fused GEMM + bias + ReLU ----------------
// Y[o,n] = relu( sum_k A[o,k] * X[k,n] + bias[o] ), per-batch.
// BM=128 (all Cout), BN=64, BK=16; 256 threads, TM=8, TN=4.
__global__ __launch_bounds__(256) void gemm_bn_relu(
    const float* __restrict__ A, const float* __restrict__ bias,
    const float* __restrict__ X, float* __restrict__ Y,
    int K, int transOut)
{
    __shared__ __align__(16) float As[16][128];
    __shared__ __align__(16) float Bs[16][64];

    int b  = blockIdx.y;
    int n0 = blockIdx.x * 64;
    const float* Xb = X + (size_t)b * K * NIN;

    int tid = threadIdx.x;
    int tx = tid & 15;        // 0..15 -> n groups of 4
    int ty = tid >> 4;        // 0..15 -> o groups of 8

    float acc[8][4];
#pragma unroll
    for (int i = 0; i < 8; i++)
#pragma unroll
        for (int j = 0; j < 4; j++) acc[i][j] = 0.f;

    for (int k0 = 0; k0 < K; k0 += 16) {
        // A tile: 128x16, stored transposed As[k][o]
        {
            int o  = tid >> 1;
            int kk = (tid & 1) * 8;
            const float* src = A + (size_t)o * K + k0 + kk;
            float4 v0 = *(const float4*)src;
            float4 v1 = *(const float4*)(src + 4);
            As[kk + 0][o] = v0.x; As[kk + 1][o] = v0.y;
            As[kk + 2][o] = v0.z; As[kk + 3][o] = v0.w;
            As[kk + 4][o] = v1.x; As[kk + 5][o] = v1.y;
            As[kk + 6][o] = v1.z; As[kk + 7][o] = v1.w;
        }
        // B tile: 16x64
        {
            int kk = tid >> 4;
            int nn = (tid & 15) * 4;
            *(float4*)&Bs[kk][nn] =
                *(const float4*)(Xb + (size_t)(k0 + kk) * NIN + n0 + nn);
        }
        __syncthreads();

#pragma unroll
        for (int k = 0; k < 16; k++) {
            float4 a0 = *(const float4*)&As[k][ty * 8];
            float4 a1 = *(const float4*)&As[k][ty * 8 + 4];
            float4 bv = *(const float4*)&Bs[k][tx * 4];
            float av[8] = {a0.x, a0.y, a0.z, a0.w, a1.x, a1.y, a1.z, a1.w};
            float bw[4] = {bv.x, bv.y, bv.z, bv.w};
#pragma unroll
            for (int i = 0; i < 8; i++)
#pragma unroll
                for (int j = 0; j < 4; j++)
                    acc[i][j] = fmaf(av[i], bw[j], acc[i][j]);
        }
        __syncthreads();
    }

#pragma unroll
    for (int i = 0; i < 8; i++) {
        int o = ty * 8 + i;
        float bs = bias[o];
#pragma unroll
        for (int j = 0; j < 4; j++) {
            int n = n0 + tx * 4 + j;
            float y = fmaxf(acc[i][j] + bs, 0.f);
            if (!transOut)
                Y[(size_t)b * CO * NIN + (size_t)o * NIN + n] = y;
            else
                Y[(size_t)b * NIN * CO + (size_t)n * CO + o] = y;
        }
    }
}

// ---------------- top-3 NN + weighted interpolation ----------------
__device__ __forceinline__ void interp_one(
    int b, int m, float x, float y, float z,
    float d0, float d1, float d2, int i0, int i1, int i2,
    const float* __restrict__ featT, float* __restrict__ out)
{
    float no = x * x + y * y + z * z;
    float a0 = d0 + no, a1 = d1 + no, a2 = d2 + no;
    if (a0 < 0.f) a0 = 1e-7f;
    if (a1 < 0.f) a1 = 1e-7f;
    if (a2 < 0.f) a2 = 1e-7f;
    float w0 = 1.f / a0, w1 = 1.f / a1, w2 = 1.f / a2;
    float ws = 1.f / (w0 + w1 + w2);
    w0 *= ws; w1 *= ws; w2 *= ws;

    const float4* r0 = (const float4*)(featT + ((size_t)b * NIN + i0) * CO);
    const float4* r1 = (const float4*)(featT + ((size_t)b * NIN + i1) * CO);
    const float4* r2 = (const float4*)(featT + ((size_t)b * NIN + i2) * CO);
    float* op = out + (size_t)b * CO * MOUT + m;
#pragma unroll
    for (int c = 0; c < 32; c++) {
        float4 A = r0[c], B = r1[c], C = r2[c];
        op[(size_t)(4 * c + 0) * MOUT] = w0 * A.x + w1 * B.x + w2 * C.x;
        op[(size_t)(4 * c + 1) * MOUT] = w0 * A.y + w1 * B.y + w2 * C.y;
        op[(size_t)(4 * c + 2) * MOUT] = w0 * A.z + w1 * B.z + w2 * C.z;
        op[(size_t)(4 * c + 3) * MOUT] = w0 * A.w + w1 * B.w + w2 * C.w;
    }
}

__global__ __launch_bounds__(256) void dist_interp_kernel(
    const float* __restrict__ xyzout,
    const float* __restrict__ featT,
    float* __restrict__ out)
{
    __shared__ float4 sp[2048];

    int b   = blockIdx.y;
    int tid = threadIdx.x;
    int m0  = blockIdx.x * 512;
    int ma  = m0 + tid;
    int mb  = m0 + 256 + tid;

    const float* qa = xyzout + ((size_t)b * MOUT + ma) * 3;
    const float* qb = xyzout + ((size_t)b * MOUT + mb) * 3;
    float x0 = qa[0], y0 = qa[1], z0 = qa[2];
    float x1 = qb[0], y1 = qb[1], z1 = qb[2];

    float e0 = 1e30f, e1 = 1e30f, e2 = 1e30f; int ia0 = 0, ia1 = 0, ia2 = 0;
    float f0 = 1e30f, f1 = 1e30f, f2 = 1e30f; int ib0 = 0, ib1 = 0, ib2 = 0;

    const float4* pb = g_pts + b * NIN;

    for (int t = 0; t < 2; t++) {
        for (int i = tid; i < 2048; i += 256) sp[i] = pb[t * 2048 + i];
        __syncthreads();

#pragma unroll 8
        for (int j = 0; j < 2048; j++) {
            float4 P = sp[j];
            float ta = fmaf(P.x, x0, fmaf(P.y, y0, fmaf(P.z, z0, P.w)));
            float tb = fmaf(P.x, x1, fmaf(P.y, y1, fmaf(P.z, z1, P.w)));
            int g = t * 2048 + j;
            if (ta < e2) {
                if (ta < e1) {
                    e2 = e1; ia2 = ia1;
                    if (ta < e0) { e1 = e0; ia1 = ia0; e0 = ta; ia0 = g; }
                    else         { e1 = ta; ia1 = g; }
                } else { e2 = ta; ia2 = g; }
            }
            if (tb < f2) {
                if (tb < f1) {
                    f2 = f1; ib2 = ib1;
                    if (tb < f0) { f1 = f0; ib1 = ib0; f0 = tb; ib0 = g; }
                    else         { f1 = tb; ib1 = g; }
                } else { f2 = tb; ib2 = g; }
            }
        }
        __syncthreads();
    }

    interp_one(b, ma, x0, y0, z0, e0, e1, e2, ia0, ia1, ia2, featT, out);
    interp_one(b, mb, x1, y1, z1, f0, f1, f2, ib0, ib1, ib2, featT, out);
}

// ---------------- host launch ----------------
extern "C" void kernel_launch(void* const* d_in, const int* in_sizes, int n_in,
                              void* d_out, int out_size)
{
    const float* rgb    = (const float*)d_in[0];
    const float* xyzin  = (const float*)d_in[1];
    const float* xyzout = (const float*)d_in[2];
    const float* w1  = (const float*)d_in[3];
    const float* b1  = (const float*)d_in[4];
    const float* gg1 = (const float*)d_in[5];
    const float* be1 = (const float*)d_in[6];
    const float* rm1 = (const float*)d_in[7];
    const float* rv1 = (const float*)d_in[8];
    const float* w2  = (const float*)d_in[9];
    const float* b2  = (const float*)d_in[10];
    const float* gg2 = (const float*)d_in[11];
    const float* be2 = (const float*)d_in[12];
    const float* rm2 = (const float*)d_in[13];
    const float* rv2 = (const float*)d_in[14];
    const float* w3  = (const float*)d_in[15];
    const float* b3  = (const float*)d_in[16];
    const float* gg3 = (const float*)d_in[17];
    const float* be3 = (const float*)d_in[18];
    const float* rm3 = (const float*)d_in[19];
    const float* rv3 = (const float*)d_in[20];
    float* out = (float*)d_out;

    void *pWf1, *pWf2, *pWf3, *pbf, *pf1, *pf2, *pfT;
    cudaGetSymbolAddress(&pWf1, g_Wf1);
    cudaGetSymbolAddress(&pWf2, g_Wf2);
    cudaGetSymbolAddress(&pWf3, g_Wf3);
    cudaGetSymbolAddress(&pbf,  g_bf);
    cudaGetSymbolAddress(&pf1,  g_feat1);
    cudaGetSymbolAddress(&pf2,  g_feat2);
    cudaGetSymbolAddress(&pfT,  g_featT);
    float* bf = (float*)pbf;

    fold_kernel<<<256, 256>>>(w1, b1, gg1, be1, rm1, rv1,
                              w2, b2, gg2, be2, rm2, rv2,
                              w3, b3, gg3, be3, rm3, rv3);
    pts_kernel<<<64, 256>>>(xyzin);

    gemm_bn_relu<<<dim3(NIN / 64, NB), 256>>>((const float*)pWf1, bf + 0 * CO,
                                              rgb, (float*)pf1, CIN, 0);
    gemm_bn_relu<<<dim3(NIN / 64, NB), 256>>>((const float*)pWf2, bf + 1 * CO,
                                              (const float*)pf1, (float*)pf2, CO, 0);
    gemm_bn_relu<<<dim3(NIN / 64, NB), 256>>>((const float*)pWf3, bf + 2 * CO,
                                              (const float*)pf2, (float*)pfT, CO, 1);

    dist_interp_kernel<<<dim3(MOUT / 512, NB), 256>>>(xyzout, (const float*)pfT, out);
}

// round 2
// speedup vs baseline: 1.3047x; 1.3047x over previous
#include <cuda_runtime.h>
#include <math.h>

#define NIN  4096
#define MOUT 16384
#define NB   4
#define CIN  256
#define CO   128

// ---------------- device scratch (no allocations allowed) ----------------
__device__ __align__(16) float g_Wf1[CO * CIN];
__device__ __align__(16) float g_Wf2[CO * CO];
__device__ __align__(16) float g_Wf3[CO * CO];
__device__ __align__(16) float g_bf[3][CO];
__device__ __align__(16) float g_feat1[NB * CO * NIN];
__device__ __align__(16) float g_feat2[NB * CO * NIN];
__device__ __align__(16) float g_featT[NB * NIN * CO];   // (B, NIN, CO) for gather
__device__ float4 g_pts[NB * NIN];                        // (-2x,-2y,-2z, |p|^2)

// ---------------- fold BN into weights/bias ----------------
__global__ void fold_kernel(
    const float* __restrict__ w1, const float* __restrict__ b1, const float* __restrict__ gg1,
    const float* __restrict__ be1, const float* __restrict__ rm1, const float* __restrict__ rv1,
    const float* __restrict__ w2, const float* __restrict__ b2, const float* __restrict__ gg2,
    const float* __restrict__ be2, const float* __restrict__ rm2, const float* __restrict__ rv2,
    const float* __restrict__ w3, const float* __restrict__ b3, const float* __restrict__ gg3,
    const float* __restrict__ be3, const float* __restrict__ rm3, const float* __restrict__ rv3)
{
    const float eps = 1e-5f;
    int idx = blockIdx.x * blockDim.x + threadIdx.x;
    if (idx < CO * CIN) {
        int o = idx / CIN;
        g_Wf1[idx] = gg1[o] / sqrtf(rv1[o] + eps) * w1[idx];
    } else if (idx < CO * CIN + CO * CO) {
        int i = idx - CO * CIN; int o = i / CO;
        g_Wf2[i] = gg2[o] / sqrtf(rv2[o] + eps) * w2[i];
    } else if (idx < CO * CIN + 2 * CO * CO) {
        int i = idx - CO * CIN - CO * CO; int o = i / CO;
        g_Wf3[i] = gg3[o] / sqrtf(rv3[o] + eps) * w3[i];
    }
    if (idx < CO) {
        float s1 = gg1[idx] / sqrtf(rv1[idx] + eps);
        g_bf[0][idx] = s1 * (b1[idx] - rm1[idx]) + be1[idx];
        float s2 = gg2[idx] / sqrtf(rv2[idx] + eps);
        g_bf[1][idx] = s2 * (b2[idx] - rm2[idx]) + be2[idx];
        float s3 = gg3[idx] / sqrtf(rv3[idx] + eps);
        g_bf[2][idx] = s3 * (b3[idx] - rm3[idx]) + be3[idx];
    }
}

// ---------------- transform input points for the distance trick ----------------
__global__ void pts_kernel(const float* __restrict__ xyzin)
{
    int idx = blockIdx.x * blockDim.x + threadIdx.x;
    if (idx < NB * NIN) {
        const float* p = xyzin + (size_t)idx * 3;
        float x = p[0], y = p[1], z = p[2];
        g_pts[idx] = make_float4(-2.f * x, -2.f * y, -2.f * z, x * x + y * y + z * z);
    }
}

// ---------------- fused GEMM + bias + ReLU ----------------
__global__ __launch_bounds__(256) void gemm_bn_relu(
    const float* __restrict__ A, const float* __restrict__ bias,
    const float* __restrict__ X, float* __restrict__ Y,
    int K, int transOut)
{
    __shared__ __align__(16) float As[16][128];
    __shared__ __align__(16) float Bs[16][64];

    int b  = blockIdx.y;
    int n0 = blockIdx.x * 64;
    const float* Xb = X + (size_t)b * K * NIN;

    int tid = threadIdx.x;
    int tx = tid & 15;
    int ty = tid >> 4;

    float acc[8][4];
#pragma unroll
    for (int i = 0; i < 8; i++)
#pragma unroll
        for (int j = 0; j < 4; j++) acc[i][j] = 0.f;

    for (int k0 = 0; k0 < K; k0 += 16) {
        {
            int o  = tid >> 1;
            int kk = (tid & 1) * 8;
            const float* src = A + (size_t)o * K + k0 + kk;
            float4 v0 = *(const float4*)src;
            float4 v1 = *(const float4*)(src + 4);
            As[kk + 0][o] = v0.x; As[kk + 1][o] = v0.y;
            As[kk + 2][o] = v0.z; As[kk + 3][o] = v0.w;
            As[kk + 4][o] = v1.x; As[kk + 5][o] = v1.y;
            As[kk + 6][o] = v1.z; As[kk + 7][o] = v1.w;
        }
        {
            int kk = tid >> 4;
            int nn = (tid & 15) * 4;
            *(float4*)&Bs[kk][nn] =
                *(const float4*)(Xb + (size_t)(k0 + kk) * NIN + n0 + nn);
        }
        __syncthreads();

#pragma unroll
        for (int k = 0; k < 16; k++) {
            float4 a0 = *(const float4*)&As[k][ty * 8];
            float4 a1 = *(const float4*)&As[k][ty * 8 + 4];
            float4 bv = *(const float4*)&Bs[k][tx * 4];
            float av[8] = {a0.x, a0.y, a0.z, a0.w, a1.x, a1.y, a1.z, a1.w};
            float bw[4] = {bv.x, bv.y, bv.z, bv.w};
#pragma unroll
            for (int i = 0; i < 8; i++)
#pragma unroll
                for (int j = 0; j < 4; j++)
                    acc[i][j] = fmaf(av[i], bw[j], acc[i][j]);
        }
        __syncthreads();
    }

#pragma unroll
    for (int i = 0; i < 8; i++) {
        int o = ty * 8 + i;
        float bs = bias[o];
#pragma unroll
        for (int j = 0; j < 4; j++) {
            int n = n0 + tx * 4 + j;
            float y = fmaxf(acc[i][j] + bs, 0.f);
            if (!transOut)
                Y[(size_t)b * CO * NIN + (size_t)o * NIN + n] = y;
            else
                Y[(size_t)b * NIN * CO + (size_t)n * CO + o] = y;
        }
    }
}

// ---------------- top-3 NN + weighted interpolation (v2) ----------------
// 1 query per thread, 128 threads/block -> 512 blocks.
// Branchless group-of-8 min via FMNMX tree; rare insertion branch per group.
__global__ __launch_bounds__(128) void dist_interp_v2(
    const float* __restrict__ xyzout,
    const float* __restrict__ featT,
    float* __restrict__ out)
{
    __shared__ __align__(16) float4 sp[2048];

    int b   = blockIdx.y;
    int tid = threadIdx.x;
    int m   = blockIdx.x * 128 + tid;

    const float* q = xyzout + ((size_t)b * MOUT + m) * 3;
    float x0 = q[0], y0 = q[1], z0 = q[2];

    float e0 = 1e30f, e1 = 1e30f, e2 = 1e30f;
    int   i0 = 0,     i1 = 0,     i2 = 0;

    const float4* pb = g_pts + b * NIN;

    for (int t = 0; t < 2; t++) {
        for (int i = tid; i < 2048; i += 128) sp[i] = pb[t * 2048 + i];
        __syncthreads();

        int base = t * 2048;
        for (int j = 0; j < 2048; j += 8) {
            float td[8];
#pragma unroll
            for (int u = 0; u < 8; u++) {
                float4 P = sp[j + u];
                td[u] = fmaf(P.x, x0, fmaf(P.y, y0, fmaf(P.z, z0, P.w)));
            }
            float m01 = fminf(td[0], td[1]);
            float m23 = fminf(td[2], td[3]);
            float m45 = fminf(td[4], td[5]);
            float m67 = fminf(td[6], td[7]);
            float gm  = fminf(fminf(m01, m23), fminf(m45, m67));

            if (gm < e2) {
#pragma unroll
                for (int u = 0; u < 8; u++) {
                    float ta = td[u];
                    if (ta < e2) {
                        int g = base + j + u;
                        if (ta < e1) {
                            e2 = e1; i2 = i1;
                            if (ta < e0) { e1 = e0; i1 = i0; e0 = ta; i0 = g; }
                            else         { e1 = ta; i1 = g; }
                        } else { e2 = ta; i2 = g; }
                    }
                }
            }
        }
        __syncthreads();
    }

    // weighted interpolation
    float no = x0 * x0 + y0 * y0 + z0 * z0;
    float a0 = e0 + no, a1 = e1 + no, a2 = e2 + no;
    if (a0 < 0.f) a0 = 1e-7f;
    if (a1 < 0.f) a1 = 1e-7f;
    if (a2 < 0.f) a2 = 1e-7f;
    float w0 = 1.f / a0, w1 = 1.f / a1, w2 = 1.f / a2;
    float ws = 1.f / (w0 + w1 + w2);
    w0 *= ws; w1 *= ws; w2 *= ws;

    const float4* r0 = (const float4*)(featT + ((size_t)b * NIN + i0) * CO);
    const float4* r1 = (const float4*)(featT + ((size_t)b * NIN + i1) * CO);
    const float4* r2 = (const float4*)(featT + ((size_t)b * NIN + i2) * CO);
    float* op = out + (size_t)b * CO * MOUT + m;
#pragma unroll
    for (int c = 0; c < 32; c++) {
        float4 A = r0[c], B = r1[c], C = r2[c];
        op[(size_t)(4 * c + 0) * MOUT] = w0 * A.x + w1 * B.x + w2 * C.x;
        op[(size_t)(4 * c + 1) * MOUT] = w0 * A.y + w1 * B.y + w2 * C.y;
        op[(size_t)(4 * c + 2) * MOUT] = w0 * A.z + w1 * B.z + w2 * C.z;
        op[(size_t)(4 * c + 3) * MOUT] = w0 * A.w + w1 * B.w + w2 * C.w;
    }
}

// ---------------- host launch ----------------
extern "C" void kernel_launch(void* const* d_in, const int* in_sizes, int n_in,
                              void* d_out, int out_size)
{
    const float* rgb    = (const float*)d_in[0];
    const float* xyzin  = (const float*)d_in[1];
    const float* xyzout = (const float*)d_in[2];
    const float* w1  = (const float*)d_in[3];
    const float* b1  = (const float*)d_in[4];
    const float* gg1 = (const float*)d_in[5];
    const float* be1 = (const float*)d_in[6];
    const float* rm1 = (const float*)d_in[7];
    const float* rv1 = (const float*)d_in[8];
    const float* w2  = (const float*)d_in[9];
    const float* b2  = (const float*)d_in[10];
    const float* gg2 = (const float*)d_in[11];
    const float* be2 = (const float*)d_in[12];
    const float* rm2 = (const float*)d_in[13];
    const float* rv2 = (const float*)d_in[14];
    const float* w3  = (const float*)d_in[15];
    const float* b3  = (const float*)d_in[16];
    const float* gg3 = (const float*)d_in[17];
    const float* be3 = (const float*)d_in[18];
    const float* rm3 = (const float*)d_in[19];
    const float* rv3 = (const float*)d_in[20];
    float* out = (float*)d_out;

    void *pWf1, *pWf2, *pWf3, *pbf, *pf1, *pf2, *pfT;
    cudaGetSymbolAddress(&pWf1, g_Wf1);
    cudaGetSymbolAddress(&pWf2, g_Wf2);
    cudaGetSymbolAddress(&pWf3, g_Wf3);
    cudaGetSymbolAddress(&pbf,  g_bf);
    cudaGetSymbolAddress(&pf1,  g_feat1);
    cudaGetSymbolAddress(&pf2,  g_feat2);
    cudaGetSymbolAddress(&pfT,  g_featT);
    float* bf = (float*)pbf;

    fold_kernel<<<256, 256>>>(w1, b1, gg1, be1, rm1, rv1,
                              w2, b2, gg2, be2, rm2, rv2,
                              w3, b3, gg3, be3, rm3, rv3);
    pts_kernel<<<64, 256>>>(xyzin);

    gemm_bn_relu<<<dim3(NIN / 64, NB), 256>>>((const float*)pWf1, bf + 0 * CO,
                                              rgb, (float*)pf1, CIN, 0);
    gemm_bn_relu<<<dim3(NIN / 64, NB), 256>>>((const float*)pWf2, bf + 1 * CO,
                                              (const float*)pf1, (float*)pf2, CO, 0);
    gemm_bn_relu<<<dim3(NIN / 64, NB), 256>>>((const float*)pWf3, bf + 2 * CO,
                                              (const float*)pf2, (float*)pfT, CO, 1);

    dist_interp_v2<<<dim3(MOUT / 128, NB), 128>>>(xyzout, (const float*)pfT, out);
}

// round 3
// speedup vs baseline: 1.3462x; 1.0319x over previous
#include <cuda_runtime.h>
#include <math.h>

#define NIN  4096
#define MOUT 16384
#define NB   4
#define CIN  256
#define CO   128

// ---------------- device scratch (no allocations allowed) ----------------
__device__ __align__(16) float g_Wf1[CO * CIN];
__device__ __align__(16) float g_Wf2[CO * CO];
__device__ __align__(16) float g_Wf3[CO * CO];
__device__ __align__(16) float g_bf[3][CO];
__device__ __align__(16) float g_feat1[NB * CO * NIN];
__device__ __align__(16) float g_feat2[NB * CO * NIN];
__device__ __align__(16) float g_featT[NB * NIN * CO];   // (B, NIN, CO) for gather
// pair-SoA packed points: for pair p (points 2p,2p+1):
//   g_ptsPk[b][2p]   = {P0.x, P1.x, P0.y, P1.y}
//   g_ptsPk[b][2p+1] = {P0.z, P1.z, P0.w, P1.w}   (w = |p|^2, xyz pre-scaled by -2)
__device__ __align__(16) float4 g_ptsPk[NB * NIN];

// ---------------- f32x2 packed helpers ----------------
__device__ __forceinline__ unsigned long long f32x2_fma(
    unsigned long long a, unsigned long long b, unsigned long long c)
{
    unsigned long long d;
    asm("fma.rn.f32x2 %0, %1, %2, %3;" : "=l"(d) : "l"(a), "l"(b), "l"(c));
    return d;
}
__device__ __forceinline__ unsigned long long f32x2_rep(float v)
{
    unsigned long long d;
    asm("mov.b64 %0, {%1, %1};" : "=l"(d) : "f"(v));
    return d;
}
__device__ __forceinline__ void f32x2_unpack(unsigned long long v, float& lo, float& hi)
{
    asm("mov.b64 {%0, %1}, %2;" : "=f"(lo), "=f"(hi) : "l"(v));
}

// ---------------- fold BN into weights/bias ----------------
__global__ void fold_kernel(
    const float* __restrict__ w1, const float* __restrict__ b1, const float* __restrict__ gg1,
    const float* __restrict__ be1, const float* __restrict__ rm1, const float* __restrict__ rv1,
    const float* __restrict__ w2, const float* __restrict__ b2, const float* __restrict__ gg2,
    const float* __restrict__ be2, const float* __restrict__ rm2, const float* __restrict__ rv2,
    const float* __restrict__ w3, const float* __restrict__ b3, const float* __restrict__ gg3,
    const float* __restrict__ be3, const float* __restrict__ rm3, const float* __restrict__ rv3)
{
    const float eps = 1e-5f;
    int idx = blockIdx.x * blockDim.x + threadIdx.x;
    if (idx < CO * CIN) {
        int o = idx / CIN;
        g_Wf1[idx] = gg1[o] / sqrtf(rv1[o] + eps) * w1[idx];
    } else if (idx < CO * CIN + CO * CO) {
        int i = idx - CO * CIN; int o = i / CO;
        g_Wf2[i] = gg2[o] / sqrtf(rv2[o] + eps) * w2[i];
    } else if (idx < CO * CIN + 2 * CO * CO) {
        int i = idx - CO * CIN - CO * CO; int o = i / CO;
        g_Wf3[i] = gg3[o] / sqrtf(rv3[o] + eps) * w3[i];
    }
    if (idx < CO) {
        float s1 = gg1[idx] / sqrtf(rv1[idx] + eps);
        g_bf[0][idx] = s1 * (b1[idx] - rm1[idx]) + be1[idx];
        float s2 = gg2[idx] / sqrtf(rv2[idx] + eps);
        g_bf[1][idx] = s2 * (b2[idx] - rm2[idx]) + be2[idx];
        float s3 = gg3[idx] / sqrtf(rv3[idx] + eps);
        g_bf[2][idx] = s3 * (b3[idx] - rm3[idx]) + be3[idx];
    }
}

// ---------------- transform + pack input points (pair-SoA) ----------------
__global__ void pts_kernel(const float* __restrict__ xyzin)
{
    int p = blockIdx.x * blockDim.x + threadIdx.x;   // pair index
    if (p < NB * NIN / 2) {
        int b = p / (NIN / 2);
        int lp = p - b * (NIN / 2);
        const float* s0 = xyzin + ((size_t)b * NIN + 2 * lp) * 3;
        float ax = s0[0], ay = s0[1], az = s0[2];
        float bx = s0[3], by = s0[4], bz = s0[5];
        float aw = ax * ax + ay * ay + az * az;
        float bw = bx * bx + by * by + bz * bz;
        g_ptsPk[b * NIN + 2 * lp + 0] = make_float4(-2.f * ax, -2.f * bx, -2.f * ay, -2.f * by);
        g_ptsPk[b * NIN + 2 * lp + 1] = make_float4(-2.f * az, -2.f * bz, aw, bw);
    }
}

// ---------------- fused GEMM + bias + ReLU ----------------
__global__ __launch_bounds__(256) void gemm_bn_relu(
    const float* __restrict__ A, const float* __restrict__ bias,
    const float* __restrict__ X, float* __restrict__ Y,
    int K, int transOut)
{
    __shared__ __align__(16) float As[16][128];
    __shared__ __align__(16) float Bs[16][64];

    int b  = blockIdx.y;
    int n0 = blockIdx.x * 64;
    const float* Xb = X + (size_t)b * K * NIN;

    int tid = threadIdx.x;
    int tx = tid & 15;
    int ty = tid >> 4;

    float acc[8][4];
#pragma unroll
    for (int i = 0; i < 8; i++)
#pragma unroll
        for (int j = 0; j < 4; j++) acc[i][j] = 0.f;

    for (int k0 = 0; k0 < K; k0 += 16) {
        {
            int o  = tid >> 1;
            int kk = (tid & 1) * 8;
            const float* src = A + (size_t)o * K + k0 + kk;
            float4 v0 = *(const float4*)src;
            float4 v1 = *(const float4*)(src + 4);
            As[kk + 0][o] = v0.x; As[kk + 1][o] = v0.y;
            As[kk + 2][o] = v0.z; As[kk + 3][o] = v0.w;
            As[kk + 4][o] = v1.x; As[kk + 5][o] = v1.y;
            As[kk + 6][o] = v1.z; As[kk + 7][o] = v1.w;
        }
        {
            int kk = tid >> 4;
            int nn = (tid & 15) * 4;
            *(float4*)&Bs[kk][nn] =
                *(const float4*)(Xb + (size_t)(k0 + kk) * NIN + n0 + nn);
        }
        __syncthreads();

#pragma unroll
        for (int k = 0; k < 16; k++) {
            float4 a0 = *(const float4*)&As[k][ty * 8];
            float4 a1 = *(const float4*)&As[k][ty * 8 + 4];
            float4 bv = *(const float4*)&Bs[k][tx * 4];
            float av[8] = {a0.x, a0.y, a0.z, a0.w, a1.x, a1.y, a1.z, a1.w};
            float bw[4] = {bv.x, bv.y, bv.z, bv.w};
#pragma unroll
            for (int i = 0; i < 8; i++)
#pragma unroll
                for (int j = 0; j < 4; j++)
                    acc[i][j] = fmaf(av[i], bw[j], acc[i][j]);
        }
        __syncthreads();
    }

#pragma unroll
    for (int i = 0; i < 8; i++) {
        int o = ty * 8 + i;
        float bs = bias[o];
#pragma unroll
        for (int j = 0; j < 4; j++) {
            int n = n0 + tx * 4 + j;
            float y = fmaxf(acc[i][j] + bs, 0.f);
            if (!transOut)
                Y[(size_t)b * CO * NIN + (size_t)o * NIN + n] = y;
            else
                Y[(size_t)b * NIN * CO + (size_t)n * CO + o] = y;
        }
    }
}

// ---------------- top-3 NN + weighted interpolation (v3, FFMA2) ----------------
// 1 query per thread, 128 threads/block -> 512 blocks.
// Packed f32x2: 3 FFMA2 per POINT-PAIR; branchless group-of-8 min via FMNMX tree.
__global__ __launch_bounds__(128) void dist_interp_v3(
    const float* __restrict__ xyzout,
    const float* __restrict__ featT,
    float* __restrict__ out)
{
    __shared__ __align__(16) float4 sp[2048];   // 1024 pairs per tile (2 float4 each)

    int b   = blockIdx.y;
    int tid = threadIdx.x;
    int m   = blockIdx.x * 128 + tid;

    const float* q = xyzout + ((size_t)b * MOUT + m) * 3;
    float x0 = q[0], y0 = q[1], z0 = q[2];

    unsigned long long qx = f32x2_rep(x0);
    unsigned long long qy = f32x2_rep(y0);
    unsigned long long qz = f32x2_rep(z0);

    float e0 = 1e30f, e1 = 1e30f, e2 = 1e30f;
    int   i0 = 0,     i1 = 0,     i2 = 0;

    const float4* pb = g_ptsPk + b * NIN;

    for (int t = 0; t < 2; t++) {
#pragma unroll
        for (int i = 0; i < 16; i++) sp[tid + i * 128] = pb[t * 2048 + tid + i * 128];
        __syncthreads();

        int base = t * 2048;
        for (int j = 0; j < 2048; j += 8) {      // 4 point-pairs = 8 points
            float td[8];
#pragma unroll
            for (int u = 0; u < 4; u++) {
                float4 A = sp[j + 2 * u];        // {x0,x1,y0,y1}
                float4 Bv = sp[j + 2 * u + 1];   // {z0,z1,w0,w1}
                unsigned long long xx, yy, zz, ww;
                // float4 components sit in aligned register pairs; reinterpret
                asm("mov.b64 %0, {%1, %2};" : "=l"(xx) : "f"(A.x),  "f"(A.y));
                asm("mov.b64 %0, {%1, %2};" : "=l"(yy) : "f"(A.z),  "f"(A.w));
                asm("mov.b64 %0, {%1, %2};" : "=l"(zz) : "f"(Bv.x), "f"(Bv.y));
                asm("mov.b64 %0, {%1, %2};" : "=l"(ww) : "f"(Bv.z), "f"(Bv.w));
                unsigned long long d =
                    f32x2_fma(xx, qx, f32x2_fma(yy, qy, f32x2_fma(zz, qz, ww)));
                f32x2_unpack(d, td[2 * u], td[2 * u + 1]);
            }
            float m01 = fminf(td[0], td[1]);
            float m23 = fminf(td[2], td[3]);
            float m45 = fminf(td[4], td[5]);
            float m67 = fminf(td[6], td[7]);
            float gm  = fminf(fminf(m01, m23), fminf(m45, m67));

            if (gm < e2) {
#pragma unroll
                for (int u = 0; u < 8; u++) {
                    float ta = td[u];
                    if (ta < e2) {
                        int g = base + j + u;
                        if (ta < e1) {
                            e2 = e1; i2 = i1;
                            if (ta < e0) { e1 = e0; i1 = i0; e0 = ta; i0 = g; }
                            else         { e1 = ta; i1 = g; }
                        } else { e2 = ta; i2 = g; }
                    }
                }
            }
        }
        __syncthreads();
    }

    // weighted interpolation
    float no = x0 * x0 + y0 * y0 + z0 * z0;
    float a0 = e0 + no, a1 = e1 + no, a2 = e2 + no;
    if (a0 < 0.f) a0 = 1e-7f;
    if (a1 < 0.f) a1 = 1e-7f;
    if (a2 < 0.f) a2 = 1e-7f;
    float w0 = 1.f / a0, w1 = 1.f / a1, w2 = 1.f / a2;
    float ws = 1.f / (w0 + w1 + w2);
    w0 *= ws; w1 *= ws; w2 *= ws;

    const float4* r0 = (const float4*)(featT + ((size_t)b * NIN + i0) * CO);
    const float4* r1 = (const float4*)(featT + ((size_t)b * NIN + i1) * CO);
    const float4* r2 = (const float4*)(featT + ((size_t)b * NIN + i2) * CO);
    float* op = out + (size_t)b * CO * MOUT + m;
#pragma unroll
    for (int c = 0; c < 32; c++) {
        float4 A = r0[c], B = r1[c], C = r2[c];
        op[(size_t)(4 * c + 0) * MOUT] = w0 * A.x + w1 * B.x + w2 * C.x;
        op[(size_t)(4 * c + 1) * MOUT] = w0 * A.y + w1 * B.y + w2 * C.y;
        op[(size_t)(4 * c + 2) * MOUT] = w0 * A.z + w1 * B.z + w2 * C.z;
        op[(size_t)(4 * c + 3) * MOUT] = w0 * A.w + w1 * B.w + w2 * C.w;
    }
}

// ---------------- host launch ----------------
extern "C" void kernel_launch(void* const* d_in, const int* in_sizes, int n_in,
                              void* d_out, int out_size)
{
    const float* rgb    = (const float*)d_in[0];
    const float* xyzin  = (const float*)d_in[1];
    const float* xyzout = (const float*)d_in[2];
    const float* w1  = (const float*)d_in[3];
    const float* b1  = (const float*)d_in[4];
    const float* gg1 = (const float*)d_in[5];
    const float* be1 = (const float*)d_in[6];
    const float* rm1 = (const float*)d_in[7];
    const float* rv1 = (const float*)d_in[8];
    const float* w2  = (const float*)d_in[9];
    const float* b2  = (const float*)d_in[10];
    const float* gg2 = (const float*)d_in[11];
    const float* be2 = (const float*)d_in[12];
    const float* rm2 = (const float*)d_in[13];
    const float* rv2 = (const float*)d_in[14];
    const float* w3  = (const float*)d_in[15];
    const float* b3  = (const float*)d_in[16];
    const float* gg3 = (const float*)d_in[17];
    const float* be3 = (const float*)d_in[18];
    const float* rm3 = (const float*)d_in[19];
    const float* rv3 = (const float*)d_in[20];
    float* out = (float*)d_out;

    void *pWf1, *pWf2, *pWf3, *pbf, *pf1, *pf2, *pfT;
    cudaGetSymbolAddress(&pWf1, g_Wf1);
    cudaGetSymbolAddress(&pWf2, g_Wf2);
    cudaGetSymbolAddress(&pWf3, g_Wf3);
    cudaGetSymbolAddress(&pbf,  g_bf);
    cudaGetSymbolAddress(&pf1,  g_feat1);
    cudaGetSymbolAddress(&pf2,  g_feat2);
    cudaGetSymbolAddress(&pfT,  g_featT);
    float* bf = (float*)pbf;

    fold_kernel<<<256, 256>>>(w1, b1, gg1, be1, rm1, rv1,
                              w2, b2, gg2, be2, rm2, rv2,
                              w3, b3, gg3, be3, rm3, rv3);
    pts_kernel<<<32, 256>>>(xyzin);

    gemm_bn_relu<<<dim3(NIN / 64, NB), 256>>>((const float*)pWf1, bf + 0 * CO,
                                              rgb, (float*)pf1, CIN, 0);
    gemm_bn_relu<<<dim3(NIN / 64, NB), 256>>>((const float*)pWf2, bf + 1 * CO,
                                              (const float*)pf1, (float*)pf2, CO, 0);
    gemm_bn_relu<<<dim3(NIN / 64, NB), 256>>>((const float*)pWf3, bf + 2 * CO,
                                              (const float*)pf2, (float*)pfT, CO, 1);

    dist_interp_v3<<<dim3(MOUT / 128, NB), 128>>>(xyzout, (const float*)pfT, out);
}